// round 1
// baseline (speedup 1.0000x reference)
#include <cuda_runtime.h>
#include <cuda_bf16.h>

// Problem constants from reference: B=128, N=512, K=N-2=510 diagonals (offsets 1..510)
#define NN 512
#define KDIAGS 510
#define THREADS 512

__global__ __launch_bounds__(THREADS, 1)
void diag_stats_kernel(const float* __restrict__ S, float* __restrict__ out,
                       int B, int out_size) {
    const int b = blockIdx.x;
    const int k = threadIdx.x;           // diagonal index 0..511 (only 0..509 valid)
    const float* __restrict__ M = S + (size_t)b * NN * NN;

    float sum = 0.0f, sumsq = 0.0f;
    float scaled = 0.0f;

    if (k < KDIAGS) {
        const int len = NN - 1 - k;      // 511 down to 2
        // Thread k walks diagonal (offset k+1): element p -> M[p*NN + p + k + 1].
        // Within a warp, consecutive k -> consecutive columns: fully coalesced.
        const float* ptr = M + (k + 1);
        #pragma unroll 8
        for (int p = 0; p < len; ++p) {
            float x = ptr[p * (NN + 1)];
            sum   += x;
            sumsq += x * x;
        }
        const float flen = (float)len;
        const float mean = sum / flen;
        float var = (sumsq - sum * mean) / (flen - 1.0f);
        var = fmaxf(var, 0.0f);          // guard fp cancellation
        scaled = sqrtf(var) * flen * 0.2f;
    }

    // Block reduction of 'scaled' over all 512 threads (invalid lanes contribute 0)
    __shared__ float red[THREADS];
    red[k] = scaled;
    __syncthreads();
    #pragma unroll
    for (int s = THREADS / 2; s >= 32; s >>= 1) {
        if (k < s) red[k] += red[k + s];
        __syncthreads();
    }
    if (k < 32) {
        float v = red[k];
        #pragma unroll
        for (int off = 16; off > 0; off >>= 1)
            v += __shfl_down_sync(0xFFFFFFFFu, v, off);
        if (k == 0) {
            float loss = v / (float)KDIAGS;
            out[b] = loss;
            if (out_size >= 2 * B) out[B + b] = loss;   // tuple: (loss, stop_gradient(loss))
        }
    }
}

extern "C" void kernel_launch(void* const* d_in, const int* in_sizes, int n_in,
                              void* d_out, int out_size) {
    const float* S = (const float*)d_in[0];
    float* out = (float*)d_out;
    const int B = in_sizes[0] / (NN * NN);
    diag_stats_kernel<<<B, THREADS>>>(S, out, B, out_size);
}

// round 2
// speedup vs baseline: 1.1252x; 1.1252x over previous
#include <cuda_runtime.h>
#include <cuda_bf16.h>

// B=128, N=512, K=510 diagonals (offsets 1..510). Output: loss[B] twice.
#define NN     512
#define KD     510
#define PAIRS  255      // pair t <-> 509-t, t=0..254, total len per pair = 513
#define TPB    1024
#define NSEG   4

__global__ __launch_bounds__(TPB, 1)
void diag_stats_kernel(const float* __restrict__ S, float* __restrict__ out,
                       int B, int out_size) {
    const int b   = blockIdx.x;
    const int tid = threadIdx.x;
    const int pid = tid & 255;      // pair id (0..254 valid)
    const int seg = tid >> 8;       // p-stride phase 0..3
    const float* __restrict__ M = S + (size_t)b * NN * NN;

    float sA = 0.f, qA = 0.f, sB = 0.f, qB = 0.f;

    if (pid < PAIRS) {
        const int lenA = 511 - pid;          // diag dA = pid      (offset pid+1)
        const int lenB = 2 + pid;            // diag dB = 509-pid  (offset 510-pid)
        const float* pa = M + pid + 1;       // element p at pa[p*513]
        const float* pb = M + 510 - pid;     // element p at pb[p*513]

        // Strided p-split: all lanes in a warp share 'seg' -> same row p ->
        // consecutive pid -> contiguous columns -> one 128B line per warp-load.
        #pragma unroll 4
        for (int p = seg; p < lenA; p += NSEG) {
            float x = pa[p * (NN + 1)];
            sA += x; qA += x * x;
        }
        #pragma unroll 4
        for (int p = seg; p < lenB; p += NSEG) {
            float x = pb[p * (NN + 1)];
            sB += x; qB += x * x;
        }
    }

    // Combine the 4 segment partials per pair via shared memory.
    __shared__ float sh[4][NSEG][256];   // [value][seg][pid] = 16 KB
    sh[0][seg][pid] = sA;
    sh[1][seg][pid] = qA;
    sh[2][seg][pid] = sB;
    sh[3][seg][pid] = qB;
    __syncthreads();

    __shared__ float red[256];
    if (seg == 0) {
        float contrib = 0.f;
        if (pid < PAIRS) {
            float SA = sh[0][0][pid] + sh[0][1][pid] + sh[0][2][pid] + sh[0][3][pid];
            float QA = sh[1][0][pid] + sh[1][1][pid] + sh[1][2][pid] + sh[1][3][pid];
            float SB = sh[2][0][pid] + sh[2][1][pid] + sh[2][2][pid] + sh[2][3][pid];
            float QB = sh[3][0][pid] + sh[3][1][pid] + sh[3][2][pid] + sh[3][3][pid];

            const float lA = (float)(511 - pid);
            const float lB = (float)(2 + pid);

            float mA = SA / lA;
            float vA = fmaxf((QA - SA * mA) / (lA - 1.0f), 0.0f);
            float mB = SB / lB;
            float vB = fmaxf((QB - SB * mB) / (lB - 1.0f), 0.0f);

            contrib = sqrtf(vA) * lA * 0.2f + sqrtf(vB) * lB * 0.2f;
        }
        red[pid] = contrib;
    }
    __syncthreads();

    // Block-reduce 256 values (tree + warp shuffle), all threads reach barriers.
    #pragma unroll
    for (int s = 128; s >= 32; s >>= 1) {
        if (tid < s) red[tid] += red[tid + s];
        __syncthreads();
    }
    if (tid < 32) {
        float v = red[tid];
        #pragma unroll
        for (int off = 16; off > 0; off >>= 1)
            v += __shfl_down_sync(0xFFFFFFFFu, v, off);
        if (tid == 0) {
            float loss = v / (float)KD;
            out[b] = loss;
            if (out_size >= 2 * B) out[B + b] = loss;   // (loss, stop_gradient(loss))
        }
    }
}

extern "C" void kernel_launch(void* const* d_in, const int* in_sizes, int n_in,
                              void* d_out, int out_size) {
    const float* S = (const float*)d_in[0];
    float* out = (float*)d_out;
    const int B = in_sizes[0] / (NN * NN);
    diag_stats_kernel<<<B, TPB>>>(S, out, B, out_size);
}